// round 3
// baseline (speedup 1.0000x reference)
#include <cuda_runtime.h>

typedef unsigned long long ull;

// ---------------- scratch (device globals; no allocation allowed) ----------------
__device__ float g_Wp[192 * 128];                       // permutation-adjusted W
__device__ float g_Tu[(size_t)500000 * 128];            // user table  (256 MB)
__device__ float g_Ti[(size_t)100000 * 128];            // item table  (51 MB)
__device__ int   g_is64;                                // adj dtype flag
__device__ int   g_swap;                                // adjA/adjB swap flag

// ---------------- threefry2x32 core ----------------
__device__ __forceinline__ unsigned rotl32(unsigned x, int d) {
    return (x << d) | (x >> (32 - d));
}

__device__ void threefry2x32(unsigned k0, unsigned k1, unsigned& x0, unsigned& x1) {
    unsigned k2 = k0 ^ k1 ^ 0x1BD11BDAu;
    x0 += k0; x1 += k1;
    const int R0[4] = {13, 15, 26, 6};
    const int R1[4] = {17, 29, 16, 24};
#pragma unroll
    for (int i = 0; i < 4; i++) { x0 += x1; x1 = rotl32(x1, R0[i]); x1 ^= x0; }
    x0 += k1; x1 += k2 + 1u;
#pragma unroll
    for (int i = 0; i < 4; i++) { x0 += x1; x1 = rotl32(x1, R1[i]); x1 ^= x0; }
    x0 += k2; x1 += k0 + 2u;
#pragma unroll
    for (int i = 0; i < 4; i++) { x0 += x1; x1 = rotl32(x1, R0[i]); x1 ^= x0; }
    x0 += k0; x1 += k1 + 3u;
#pragma unroll
    for (int i = 0; i < 4; i++) { x0 += x1; x1 = rotl32(x1, R1[i]); x1 ^= x0; }
    x0 += k1; x1 += k2 + 4u;
#pragma unroll
    for (int i = 0; i < 4; i++) { x0 += x1; x1 = rotl32(x1, R0[i]); x1 ^= x0; }
    x0 += k2; x1 += k0 + 5u;
}

// ---------------- K0: jax PARTITIONABLE threefry -> reordered W, + probes -------
// jax >= 0.4.36 default (jax_threefry_partitionable=True):
//   split(key) foldlike: subkey = TF(key, (hi=0, lo=1))  [full 2-word output]
//   random_bits(subkey, 32, (64,)): bits[i] = x0 ^ x1 of TF(subkey, (hi=0, lo=i))
//   _shuffle: num_rounds = ceil(3*ln(64)/ln(2^32-1)) = 1 round
//   perm = sort_key_val(bits, arange(64)) (stable)
// Contribution: ru[:,c] = uf[:,perm[c]] -> Wp[64+t] = W[64 + rank(bits[t])]
__global__ void k_build_wp(const float* __restrict__ W,
                           const void* __restrict__ adjA) {
    __shared__ unsigned bits[2][64];
    __shared__ unsigned subk[2][2];
    __shared__ int src[192];
    const int t = threadIdx.x;
    const int s = (t < 128) ? (t >> 6) : -1;   // seed group: 0->42, 1->43
    const int i = t & 63;

    if (t < 192) src[t] = t;                   // review block stays identity

    if (t < 2) {                               // foldlike split: subkey = TF(key,(0,1))
        unsigned x0 = 0u, x1 = 1u;
        threefry2x32(0u, 42u + (unsigned)t, x0, x1);
        subk[t][0] = x0; subk[t][1] = x1;
    }
    if (t == 128) {  // int64 vs int32 probe: odd int32 slots all zero => int64
        const int* p = (const int*)adjA;
        int all0 = 1;
        for (int j = 1; j < 128; j += 2) all0 &= (p[j] == 0);
        g_is64 = all0;
    }
    __syncthreads();
    if (t == 129) {  // adjA has values >= 100000 => adjA is adj_u (no swap)
        int big = 0;
        if (g_is64) {
            const long long* a = (const long long*)adjA;
            for (int j = 0; j < 4096; j++) big |= (a[j] >= 100000);
        } else {
            const int* a = (const int*)adjA;
            for (int j = 0; j < 4096; j++) big |= (a[j] >= 100000);
        }
        g_swap = !big;
    }

    if (s >= 0) {   // partitionable random_bits: counter (0, i), output x0^x1
        unsigned x0 = 0u, x1 = (unsigned)i;
        threefry2x32(subk[s][0], subk[s][1], x0, x1);
        bits[s][i] = x0 ^ x1;
    }
    __syncthreads();

    if (s >= 0) {   // stable rank; Wp[block+i] = W[block+rank_i]
        unsigned kv = bits[s][i];
        int r = 0;
        for (int j = 0; j < 64; j++) {
            unsigned kj = bits[s][j];
            r += (kj < kv) || (kj == kv && j < i);
        }
        src[(s + 1) * 64 + i] = (s + 1) * 64 + r;
    }
    __syncthreads();

    for (int idx = t; idx < 192 * 128; idx += blockDim.x)
        g_Wp[idx] = W[src[idx >> 7] * 128 + (idx & 127)];
}

// ---------------- packed f32x2 helpers ----------------
__device__ __forceinline__ ull pk2(float x, float y) {
    ull r; asm("mov.b64 %0, {%1, %2};" : "=l"(r) : "f"(x), "f"(y)); return r;
}
__device__ __forceinline__ float2 upk2(ull v) {
    float2 f; asm("mov.b64 {%0, %1}, %2;" : "=f"(f.x), "=f"(f.y) : "l"(v)); return f;
}
__device__ __forceinline__ ull fma2_(ull a, ull b, ull c) {
    ull d; asm("fma.rn.f32x2 %0, %1, %2, %3;" : "=l"(d) : "l"(a), "l"(b), "l"(c)); return d;
}

// ---------------- GEMM: C[M,128] = A[M,64] @ g_Wp[koff:koff+64, :] (+ epilogue) ----
// MODE 0: A=item  -> g_Ti               (koff=128)
// MODE 1: A=user  -> g_Tu               (koff=64)
// MODE 2: A=review-> out = relu(. + g_Tu[adj_u] + g_Ti[adj_i])   (koff=0)
// Block: 128 threads, tile 64 rows x 128 cols; thread = 8 rows x 8 cols (f32x2 x4).
template <int MODE>
__global__ __launch_bounds__(128, 4)
void k_gemm(const float* __restrict__ A, int M, float* __restrict__ Cout,
            const void* __restrict__ adjA, const void* __restrict__ adjB) {
    constexpr int KOFF = (MODE == 2) ? 0 : (MODE == 1 ? 64 : 128);

    __shared__ __align__(16) float Bs[64 * 128];   // 32 KB
    __shared__ __align__(16) float At[32 * 65];    // 8.3 KB, transposed A chunk (ld=65)
    __shared__ int s_au[64], s_ai[64];

    const int t = threadIdx.x;
    const int row0 = blockIdx.x * 64;
    const int tx = t & 15, ty = t >> 4;
    const int c0 = tx * 8, r0 = ty * 8;

    // load full B block (64x128) once
    {
        const float4* src4 = (const float4*)(g_Wp + KOFF * 128);
        float4* b4 = (float4*)Bs;
#pragma unroll
        for (int i = 0; i < 16; i++) b4[i * 128 + t] = src4[i * 128 + t];
    }
    // gather indices for epilogue
    if (MODE == 2 && t < 64) {
        const void* aU = g_swap ? adjB : adjA;
        const void* aI = g_swap ? adjA : adjB;
        int gr = row0 + t;
        if (gr < M) {
            if (g_is64) {
                s_au[t] = (int)((const long long*)aU)[gr];
                s_ai[t] = (int)((const long long*)aI)[gr];
            } else {
                s_au[t] = ((const int*)aU)[gr];
                s_ai[t] = ((const int*)aI)[gr];
            }
        } else { s_au[t] = 0; s_ai[t] = 0; }
    }

    ull acc[8][4];
#pragma unroll
    for (int i = 0; i < 8; i++)
#pragma unroll
        for (int j = 0; j < 4; j++) acc[i][j] = 0ull;

    // two K-chunks of 32
#pragma unroll 1
    for (int kb = 0; kb < 2; kb++) {
        const int kbase = kb * 32;
        if (kb) __syncthreads();   // previous compute done before overwrite
        // load A chunk transposed: At[k_local*65 + row]
#pragma unroll
        for (int i = 0; i < 4; i++) {
            int q = i * 128 + t;       // 0..511
            int r = q >> 3;            // 0..63
            int kc = (q & 7) << 2;     // 0..28
            int gr = row0 + r;
            float4 v = make_float4(0.f, 0.f, 0.f, 0.f);
            if (gr < M) v = *(const float4*)(A + (size_t)gr * 64 + kbase + kc);
            At[(kc + 0) * 65 + r] = v.x;
            At[(kc + 1) * 65 + r] = v.y;
            At[(kc + 2) * 65 + r] = v.z;
            At[(kc + 3) * 65 + r] = v.w;
        }
        __syncthreads();

#pragma unroll 8
        for (int k = 0; k < 32; k++) {
            const float* brow = Bs + (kbase + k) * 128 + c0;
            ulonglong2 bA = *(const ulonglong2*)(brow);
            ulonglong2 bB = *(const ulonglong2*)(brow + 4);
            const float* ap = At + k * 65 + r0;
#pragma unroll
            for (int i = 0; i < 8; i++) {
                float a = ap[i];
                ull ad = pk2(a, a);
                acc[i][0] = fma2_(ad, bA.x, acc[i][0]);
                acc[i][1] = fma2_(ad, bA.y, acc[i][1]);
                acc[i][2] = fma2_(ad, bB.x, acc[i][2]);
                acc[i][3] = fma2_(ad, bB.y, acc[i][3]);
            }
        }
    }

    // epilogue
#pragma unroll
    for (int i = 0; i < 8; i++) {
        int lr = r0 + i;
        int gr = row0 + lr;
        if (gr >= M) continue;
        float2 p0 = upk2(acc[i][0]), p1 = upk2(acc[i][1]);
        float2 p2 = upk2(acc[i][2]), p3 = upk2(acc[i][3]);
        if (MODE == 2) {
            const float4* tu = (const float4*)(g_Tu + ((size_t)s_au[lr] << 7) + c0);
            const float4* ti = (const float4*)(g_Ti + ((size_t)s_ai[lr] << 7) + c0);
            float4 u0 = tu[0], u1 = tu[1];
            float4 v0 = ti[0], v1 = ti[1];
            float4 o0, o1;
            o0.x = fmaxf(p0.x + u0.x + v0.x, 0.f);
            o0.y = fmaxf(p0.y + u0.y + v0.y, 0.f);
            o0.z = fmaxf(p1.x + u0.z + v0.z, 0.f);
            o0.w = fmaxf(p1.y + u0.w + v0.w, 0.f);
            o1.x = fmaxf(p2.x + u1.x + v1.x, 0.f);
            o1.y = fmaxf(p2.y + u1.y + v1.y, 0.f);
            o1.z = fmaxf(p3.x + u1.z + v1.z, 0.f);
            o1.w = fmaxf(p3.y + u1.w + v1.w, 0.f);
            float4* dst = (float4*)(Cout + ((size_t)gr << 7) + c0);
            dst[0] = o0; dst[1] = o1;
        } else {
            float* T = (MODE == 0) ? g_Ti : g_Tu;
            float4 o0 = make_float4(p0.x, p0.y, p1.x, p1.y);
            float4 o1 = make_float4(p2.x, p2.y, p3.x, p3.y);
            float4* dst = (float4*)(T + ((size_t)gr << 7) + c0);
            dst[0] = o0; dst[1] = o1;
        }
    }
}

// ---------------- launch ----------------
extern "C" void kernel_launch(void* const* d_in, const int* in_sizes, int n_in,
                              void* d_out, int out_size) {
    // classify inputs by element count (robust to metadata ordering)
    const float *review = nullptr, *user = nullptr, *item = nullptr, *W = nullptr;
    const void *adjA = nullptr, *adjB = nullptr;
    int n_r = 1000000, n_u = 500000, n_i = 100000;
    for (int k = 0; k < n_in; k++) {
        long long sz = in_sizes[k];
        if (sz == 64000000)      { review = (const float*)d_in[k]; n_r = (int)(sz / 64); }
        else if (sz == 32000000) { user   = (const float*)d_in[k]; n_u = (int)(sz / 64); }
        else if (sz == 6400000)  { item   = (const float*)d_in[k]; n_i = (int)(sz / 64); }
        else if (sz == 24576)    { W      = (const float*)d_in[k]; }
        else if (!adjA)          { adjA   = d_in[k]; }
        else                     { adjB   = d_in[k]; }
    }
    // fallback to declared order if classification failed
    if (!review || !user || !item || !W || !adjA || !adjB) {
        review = (const float*)d_in[0]; user = (const float*)d_in[1];
        item   = (const float*)d_in[2]; W    = (const float*)d_in[3];
        adjA   = d_in[4];               adjB = d_in[5];
        n_r = in_sizes[0] / 64; n_u = in_sizes[1] / 64; n_i = in_sizes[2] / 64;
    }
    float* out = (float*)d_out;

    k_build_wp<<<1, 256>>>(W, adjA);
    k_gemm<0><<<(n_i + 63) / 64, 128>>>(item,   n_i, nullptr, nullptr, nullptr);
    k_gemm<1><<<(n_u + 63) / 64, 128>>>(user,   n_u, nullptr, nullptr, nullptr);
    k_gemm<2><<<(n_r + 63) / 64, 128>>>(review, n_r, out,     adjA,    adjB);
}